// round 12
// baseline (speedup 1.0000x reference)
#include <cuda_runtime.h>
#include <cuda_bf16.h>

// Problem constants (B=4, 96^3 vol, 4^3 patches, E=768)
#define TOKENS   13824
#define MASKN    10368
#define UNMASKN  3456
#define EDIM     768
#define KDIM     64
#define KPAIRS   96            // K' = 3*KDIM = 192 bf16 -> 96 bf16x2 pairs
#define KSTEPS   12
#define TT       32            // tokens per block
#define NTHREADS 768
#define UT32     (UNMASKN / TT)   // 108
#define MT32     (MASKN / TT)     // 324
#define BATCH    4
#define AROW     99            // padded A' row stride (uint32 words)
#define BROW     776           // padded B stage row stride (uint32 words)
#define LOG2_1E4 13.287712379549449f

// positional-encoding table: g_pe[pos][c] = (c even ? sin : cos)(pos * 10000^-((c>>1)/128))
__device__ float g_pe[24][256];
// split weights, expanded K'=192, packed bf16x2 pairs: g_B2[p][e] = (B'[2p][e], B'[2p+1][e])
// B'[k'][e]: k'=3m+r, r==1 -> Wlo[m][e], else Whi[m][e]
__device__ unsigned int g_B2[KPAIRS][EDIM];

__device__ __forceinline__ unsigned int bf16pair(float lo, float hi) {
    __nv_bfloat162 h = __floats2bfloat162_rn(lo, hi);   // .x = lo half
    return *reinterpret_cast<unsigned int*>(&h);
}

__device__ __forceinline__ void mma_bf16(float* c,
    unsigned int a0, unsigned int a1, unsigned int a2, unsigned int a3,
    unsigned int b0, unsigned int b1) {
    asm volatile(
        "mma.sync.aligned.m16n8k16.row.col.f32.bf16.bf16.f32 "
        "{%0,%1,%2,%3}, {%4,%5,%6,%7}, {%8,%9}, {%0,%1,%2,%3};"
        : "+f"(c[0]), "+f"(c[1]), "+f"(c[2]), "+f"(c[3])
        : "r"(a0), "r"(a1), "r"(a2), "r"(a3), "r"(b0), "r"(b1));
}

// Blocks [0,24): pe table. Blocks [24,..): mask_idx tail.
__global__ __launch_bounds__(256)
void init_pe_kernel(const int* __restrict__ perm, float* __restrict__ tail_out, int n_tail) {
    const int bi = blockIdx.x, tid = threadIdx.x;
    if (bi < 24) {
        const float invf = exp2f(-(float)(tid >> 1) * (LOG2_1E4 / 128.0f));
        float s, c;
        sincosf((float)bi * invf, &s, &c);
        g_pe[bi][tid] = (tid & 1) ? c : s;
    } else {
        const int i = (bi - 24) * 256 + tid;
        if (i < n_tail) tail_out[i] = (float)perm[i];
    }
}

// Precompute split W into packed bf16x2 pairs. 96*768/256 = 288 blocks.
__global__ __launch_bounds__(256)
void init_w_kernel(const float* __restrict__ W) {
    const int idx = blockIdx.x * 256 + threadIdx.x;
    const int p = idx / EDIM, e = idx % EDIM;
    float v[2];
    #pragma unroll
    for (int i = 0; i < 2; i++) {
        const int kp = 2 * p + i, m = kp / 3, r = kp - 3 * m;
        const float wv = W[m * EDIM + e];
        const float wh = __bfloat162float(__float2bfloat16_rn(wv));
        v[i] = (r == 1) ? (wv - wh) : wv;   // bf16pair rounds
    }
    g_B2[p][e] = bf16pair(v[0], v[1]);
}

// One block: 32 tokens x 768 dims via bf16-split tensor MMA + fused bias/pe/LN.
// B stage DOUBLE-BUFFERED: LDG for kstep+1 issued before the MMAs of kstep,
// STS into the other buffer, ONE barrier per kstep (vs 2 in the naive version).
// 24 warps = 2 token-bands(16) x 12 dim-groups(64).
// Blocks [0, 432): unmask per batch. Blocks [432, 756): mask tokens once, written x4.
__global__ __launch_bounds__(NTHREADS, 1)
void embed_kernel(const float* __restrict__ x,
                  const float* __restrict__ bias,
                  const float* __restrict__ mtok,
                  const float* __restrict__ gamma,
                  const float* __restrict__ beta,
                  const int*   __restrict__ perm,
                  float* __restrict__ out)
{
    __shared__ __align__(16) unsigned int As[TT][AROW];       // A' packed bf16x2
    __shared__ __align__(16) unsigned int Bs[2][8][BROW];     // B' double-buffered stage
    __shared__ int   sH[TT], sW[TT], sD[TT];
    __shared__ float redS[TT][13], redQ[TT][13];
    __shared__ float meanv[TT], rstdv[TT];

    const int tid  = threadIdx.x;
    const int lane = tid & 31;
    const int w    = tid >> 5;
    const int g    = lane >> 2;      // row within m16 (0..7)
    const int tg   = lane & 3;       // thread in group
    const int band = w / 12;         // token band (16 tokens)
    const int dg   = w % 12;         // dim group (64 dims)

    const int bi = blockIdx.x;
    const bool is_mask = bi >= BATCH * UT32;
    int b = 0, tile;
    if (!is_mask) { b = bi / UT32; tile = bi % UT32; }
    else          { tile = bi - BATCH * UT32; }

    // ---- acc init with bias ----
    const int ebase = dg * 64 + 2 * tg;
    float acc[8][4];
    #pragma unroll
    for (int j = 0; j < 8; j++) {
        const float2 bb = *(const float2*)(bias + ebase + 8 * j);
        acc[j][0] = bb.x; acc[j][1] = bb.y; acc[j][2] = bb.x; acc[j][3] = bb.y;
    }

    // ---- B stage prologue for ks = 0 (also warms the LDG pipe) ----
    const int i0 = tid, i1 = tid + 768;           // 1536 uint4-chunks: 8 rows x 192
    const int r0 = i0 / 192, c0 = (i0 % 192) * 4;
    const int r1 = i1 / 192, c1 = (i1 % 192) * 4;
    uint4 nb0 = __ldg((const uint4*)&g_B2[r0][c0]);
    uint4 nb1 = __ldg((const uint4*)&g_B2[r1][c1]);

    // ---- stage A': gather 32 patch rows, bf16-split, expand K'=192 ----
    if (tid < 512) {
        const int tok = tid & 31;
        const int seg = tid >> 5;     // 0..15, 4 k-values each
        const int m   = tile * TT + tok;
        const int s   = is_mask ? perm[m] : perm[MASKN + m];
        const int h = s / 576, wq = (s % 576) / 24, d = s % 24;
        if (seg == 0) { sH[tok] = h; sW[tok] = wq; sD[tok] = d; }
        float4 v;
        if (!is_mask) {
            const int i = seg >> 2, j = seg & 3;
            const size_t xi = (((size_t)(b * 96 + 4 * h + i)) * 96 + (4 * wq + j)) * 96 + 4 * d;
            v = *(const float4*)(x + xi);
        } else {
            v = *(const float4*)(mtok + (size_t)m * KDIM + seg * 4);
        }
        const float f0 = v.x, f1 = v.y, f2 = v.z, f3 = v.w;
        const float h0 = __bfloat162float(__float2bfloat16_rn(f0));
        const float h1 = __bfloat162float(__float2bfloat16_rn(f1));
        const float h2 = __bfloat162float(__float2bfloat16_rn(f2));
        const float h3 = __bfloat162float(__float2bfloat16_rn(f3));
        unsigned int* ar = &As[tok][6 * seg];
        ar[0] = bf16pair(f0,      f0);        // (Ah0, Ah0)
        ar[1] = bf16pair(f0 - h0, f1);        // (Al0, Ah1)
        ar[2] = bf16pair(f1,      f1 - h1);   // (Ah1, Al1)
        ar[3] = bf16pair(f2,      f2);        // (Ah2, Ah2)
        ar[4] = bf16pair(f2 - h2, f3);        // (Al2, Ah3)
        ar[5] = bf16pair(f3,      f3 - h3);   // (Ah3, Al3)
    }

    // commit prologue B stage
    *(uint4*)&Bs[0][r0][c0] = nb0;
    *(uint4*)&Bs[0][r1][c1] = nb1;
    __syncthreads();

    // ---- GEMM main loop: 12 k-steps, double-buffered B, one barrier per step ----
    const int arow0 = band * 16 + g;
    const int bcol  = dg * 64 + g;
    #pragma unroll 1
    for (int ks = 0; ks < KSTEPS; ks++) {
        if (ks < KSTEPS - 1) {
            nb0 = __ldg((const uint4*)&g_B2[8 * (ks + 1) + r0][c0]);
            nb1 = __ldg((const uint4*)&g_B2[8 * (ks + 1) + r1][c1]);
        }
        const unsigned int a0 = As[arow0][8 * ks + tg];
        const unsigned int a1 = As[arow0 + 8][8 * ks + tg];
        const unsigned int a2 = As[arow0][8 * ks + tg + 4];
        const unsigned int a3 = As[arow0 + 8][8 * ks + tg + 4];
        const unsigned int (*Bcur)[BROW] = Bs[ks & 1];
        #pragma unroll
        for (int j = 0; j < 8; j++) {
            const unsigned int b0 = Bcur[tg][bcol + 8 * j];
            const unsigned int b1 = Bcur[tg + 4][bcol + 8 * j];
            mma_bf16(acc[j], a0, a1, a2, a3, b0, b1);
        }
        if (ks < KSTEPS - 1) {
            unsigned int (*Bnxt)[BROW] = Bs[(ks + 1) & 1];
            *(uint4*)&Bnxt[r0][c0] = nb0;
            *(uint4*)&Bnxt[r1][c1] = nb1;
            __syncthreads();
        }
    }

    // ---- epilogue: + positional encoding, LN stats ----
    const int t0 = band * 16 + g, t1 = t0 + 8;
    const int* sposArr = (dg < 4) ? sH : (dg < 8) ? sW : sD;
    const int pos0 = sposArr[t0], pos1 = sposArr[t1];
    const int pecol = (dg & 3) * 64 + 2 * tg;

    float s0 = 0.f, q0 = 0.f, s1 = 0.f, q1 = 0.f;
    #pragma unroll
    for (int j = 0; j < 8; j++) {
        const float2 p0 = *(const float2*)&g_pe[pos0][pecol + 8 * j];
        const float2 p1 = *(const float2*)&g_pe[pos1][pecol + 8 * j];
        acc[j][0] += p0.x; acc[j][1] += p0.y;
        acc[j][2] += p1.x; acc[j][3] += p1.y;
        s0 += acc[j][0] + acc[j][1];
        q0 += acc[j][0] * acc[j][0] + acc[j][1] * acc[j][1];
        s1 += acc[j][2] + acc[j][3];
        q1 += acc[j][2] * acc[j][2] + acc[j][3] * acc[j][3];
    }
    #pragma unroll
    for (int off = 1; off <= 2; off <<= 1) {
        s0 += __shfl_xor_sync(0xffffffffu, s0, off);
        q0 += __shfl_xor_sync(0xffffffffu, q0, off);
        s1 += __shfl_xor_sync(0xffffffffu, s1, off);
        q1 += __shfl_xor_sync(0xffffffffu, q1, off);
    }
    if (tg == 0) {
        redS[t0][dg] = s0; redQ[t0][dg] = q0;
        redS[t1][dg] = s1; redQ[t1][dg] = q1;
    }
    __syncthreads();

    if (tid < TT) {
        float sm = 0.f, sq = 0.f;
        #pragma unroll
        for (int wi = 0; wi < 12; wi++) { sm += redS[tid][wi]; sq += redQ[tid][wi]; }
        const float mn = sm * (1.0f / (float)EDIM);
        const float vr = sq * (1.0f / (float)EDIM) - mn * mn;
        meanv[tid] = mn;
        rstdv[tid] = rsqrtf(vr + 0.001f);
    }
    __syncthreads();

    const float mn0 = meanv[t0], rs0 = rstdv[t0];
    const float mn1 = meanv[t1], rs1 = rstdv[t1];

    if (!is_mask) {
        float* o0 = out + ((size_t)b * TOKENS + (size_t)tile * TT + t0) * EDIM;
        float* o1 = out + ((size_t)b * TOKENS + (size_t)tile * TT + t1) * EDIM;
        #pragma unroll
        for (int j = 0; j < 8; j++) {
            const int e = ebase + 8 * j;
            const float2 gm = *(const float2*)(gamma + e);
            const float2 bt = *(const float2*)(beta + e);
            float2 r0, r1;
            r0.x = (acc[j][0] - mn0) * rs0 * gm.x + bt.x;
            r0.y = (acc[j][1] - mn0) * rs0 * gm.y + bt.y;
            r1.x = (acc[j][2] - mn1) * rs1 * gm.x + bt.x;
            r1.y = (acc[j][3] - mn1) * rs1 * gm.y + bt.y;
            *(float2*)(o0 + e) = r0;
            *(float2*)(o1 + e) = r1;
        }
    } else {
        float* o0 = out + ((size_t)UNMASKN + (size_t)tile * TT + t0) * EDIM;
        float* o1 = out + ((size_t)UNMASKN + (size_t)tile * TT + t1) * EDIM;
        const size_t bstride = (size_t)TOKENS * EDIM;
        #pragma unroll
        for (int j = 0; j < 8; j++) {
            const int e = ebase + 8 * j;
            const float2 gm = *(const float2*)(gamma + e);
            const float2 bt = *(const float2*)(beta + e);
            float2 r0, r1;
            r0.x = (acc[j][0] - mn0) * rs0 * gm.x + bt.x;
            r0.y = (acc[j][1] - mn0) * rs0 * gm.y + bt.y;
            r1.x = (acc[j][2] - mn1) * rs1 * gm.x + bt.x;
            r1.y = (acc[j][3] - mn1) * rs1 * gm.y + bt.y;
            #pragma unroll
            for (int bb = 0; bb < BATCH; bb++) {
                *(float2*)(o0 + bb * bstride + e) = r0;
                *(float2*)(o1 + bb * bstride + e) = r1;
            }
        }
    }
}

extern "C" void kernel_launch(void* const* d_in, const int* in_sizes, int n_in,
                              void* d_out, int out_size) {
    const float* x     = (const float*)d_in[0];
    const float* W     = (const float*)d_in[1];
    const float* bias  = (const float*)d_in[2];
    const float* mtok  = (const float*)d_in[3];
    const float* gamma = (const float*)d_in[4];
    const float* beta  = (const float*)d_in[5];
    const int*   perm  = (const int*)d_in[6];
    float* out = (float*)d_out;

    const long long main_elems = (long long)BATCH * TOKENS * EDIM;  // 42,467,328
    const long long extra = (long long)out_size - main_elems;       // expected 10368 (mask_idx)
    const int n_tail = extra > 0 ? (int)extra : 0;
    const int tail_blocks = (n_tail + 255) / 256;

    init_pe_kernel<<<24 + tail_blocks, 256>>>(perm, out + main_elems, n_tail);
    init_w_kernel<<<(KPAIRS * EDIM) / 256, 256>>>(W);   // 288 blocks

    embed_kernel<<<BATCH * UT32 + MT32, NTHREADS>>>(x, bias, mtok, gamma, beta, perm, out);
}